// round 14
// baseline (speedup 1.0000x reference)
#include <cuda_runtime.h>
#include <cstdint>

#define Nn   2048
#define Ee   65536
#define INC  128
#define HIDc 32
#define LATc 16

typedef unsigned long long ull;

// ---------------- scratch (static zero; self-cleaning each run) ----------------
__device__ float g_deg [Nn];                       // edge count; reset in k_zhij
__device__ __align__(16) float g_xw  [Nn*HIDc];
__device__ __align__(16) float g_agg1[Nn*HIDc];   // reset in k_zhij
__device__ __align__(16) float g_aggh[Nn*HIDc];   // reset in k_zhij
__device__ __align__(16) float g_hi  [Nn*LATc];
__device__ __align__(16) float g_hjT [LATc*Nn];   // transposed: [l][i]

// ---------------- helpers ----------------
__device__ __forceinline__ void pdl_trigger() {    // let successor grid launch
    asm volatile("griddepcontrol.launch_dependents;");
}
__device__ __forceinline__ void pdl_wait() {       // wait: predecessor grid complete+visible
    asm volatile("griddepcontrol.wait;" ::: "memory");
}
__device__ __forceinline__ int eidx(const void* p, int pos, int is64) {
    if (is64) return (int)((const long long*)p)[pos];
    return ((const int*)p)[pos];
}
// per-block dtype detect: ids < 2048 => int64 storage has zero high words
__device__ __forceinline__ int detect64(const void* p_) {
    const ull* p = (const ull*)p_;
    ull orv = 0;
#pragma unroll
    for (int k = 0; k < 64; k++) orv |= p[k];
    return ((orv >> 32) == 0ull) ? 1 : 0;
}
__device__ __forceinline__ void red4(float* addr, float4 v) {
    asm volatile("red.global.add.v4.f32 [%0], {%1, %2, %3, %4};"
                 :: "l"(__cvta_generic_to_global(addr)),
                    "f"(v.x), "f"(v.y), "f"(v.z), "f"(v.w) : "memory");
}
__device__ __forceinline__ ull f32x2_add(ull a, ull b) {
    ull r; asm("add.rn.f32x2 %0, %1, %2;" : "=l"(r) : "l"(a), "l"(b)); return r;
}
__device__ __forceinline__ ull f32x2_fma(ull a, ull b, ull c) {
    ull r; asm("fma.rn.f32x2 %0, %1, %2, %3;" : "=l"(r) : "l"(a), "l"(b), "l"(c)); return r;
}
__device__ __forceinline__ ull pack2(float lo, float hi) {
    ull r; asm("mov.b64 %0, {%1, %2};" : "=l"(r) : "f"(lo), "f"(hi)); return r;
}
__device__ __forceinline__ float2 unpack2(ull v) {
    float2 f; asm("mov.b64 {%0, %1}, %2;" : "=f"(f.x), "=f"(f.y) : "l"(v)); return f;
}
__device__ __forceinline__ float fast_sigmoid(float x) {
    float t;
    asm("tanh.approx.f32 %0, %1;" : "=f"(t) : "f"(0.5f * x));
    return fmaf(0.5f, t, 0.5f);
}

// ---------------- kernels ----------------

// L1: deg atomics | xw = x @ W1 (8 rows/block) | zero adj_true  (all independent)
__global__ void k_pre(const void* __restrict__ ei,
                      const float* __restrict__ x, const float* __restrict__ W1,
                      float4* __restrict__ adjt4) {
    __shared__ float xs[8][INC];
    __shared__ int   s64;
    int tid = threadIdx.x;                            // 256 threads, 256 blocks
    int t   = blockIdx.x * 256 + tid;                 // 0..65535
    if (tid == 0) { pdl_trigger(); s64 = detect64(ei); }

    // zero adj_true: 16 float4 per thread (coalesced, full 16.8MB)
#pragma unroll
    for (int k = 0; k < 16; k++)
        adjt4[t + k * 65536] = make_float4(0.f, 0.f, 0.f, 0.f);

    // fill x tile for this block's 8 GEMM rows
    for (int u = tid; u < 8 * INC; u += 256) {
        int r = u / INC, k = u % INC;
        xs[r][k] = x[(blockIdx.x * 8 + r) * INC + k];
    }
    __syncthreads();

    // one degree atomic per thread
    atomicAdd(&g_deg[eidx(ei, Ee + t, s64)], 1.0f);

    // warp-per-row GEMM: row = 8*block + warp, c = lane
    int row = blockIdx.x * 8 + (tid >> 5);
    int c   = tid & 31;
    float s = 0.f;
#pragma unroll 8
    for (int k = 0; k < INC; k++) s = fmaf(xs[tid >> 5][k], W1[k * HIDc + c], s);
    g_xw[row * HIDc + c] = s;
}

// L2: eagg1 (8 threads/edge, 1 red4 each) | adj_true scatter (1 thread/edge)
__global__ void k_eagg1true(const void* __restrict__ ei,
                            const void* __restrict__ eit, float* __restrict__ adjt) {
    __shared__ int s64, s64t;
    int tx = threadIdx.x;
    if (tx == 0)  { pdl_trigger(); s64 = detect64(ei); }
    if (tx == 32) s64t = detect64(eit);
    __syncthreads();
    // ---- prologue: independent loads (edge indices) overlap predecessor tail ----
    int t = blockIdx.x * 256 + tx;                    // 524288 threads
    int e = t >> 3, c = t & 7;
    int s = eidx(ei, e, s64), d = eidx(ei, Ee + e, s64);
    int ti = eidx(eit, e, s64t), tj = eidx(eit, Ee + e, s64t);
    // ---- dependent part ----
    pdl_wait();
    if (c == 0) atomicAdd(&adjt[ti * Nn + tj], 1.0f); // adjt zeroed by k_pre
    float nw = rsqrtf((g_deg[s] + 1.0f) * (g_deg[d] + 1.0f));
    float4 a = ((const float4*)g_xw)[s * 8 + c];
    a.x *= nw; a.y *= nw; a.z *= nw; a.w *= nw;
    red4(&g_agg1[d * HIDc + c * 4], a);
}

// L3: eagg2 with h1 computed inline per edge (GCN linearity: aggregate h, multiply later)
__global__ void k_eagg2(const void* __restrict__ ei, const float* __restrict__ b1) {
    __shared__ int s64;
    if (threadIdx.x == 0) { pdl_trigger(); s64 = detect64(ei); }
    __syncthreads();
    // ---- prologue: indices + bias (independent of eagg1) ----
    int t = blockIdx.x * 256 + threadIdx.x;           // 524288 threads
    int e = t >> 3, c = t & 7;
    int s = eidx(ei, e, s64), d = eidx(ei, Ee + e, s64);
    float4 bb = ((const float4*)b1)[c];
    // ---- dependent part ----
    pdl_wait();
    float ds = g_deg[s];
    float nw = rsqrtf((ds + 1.0f) * (g_deg[d] + 1.0f));
    float d2 = 1.0f / (ds + 1.0f);
    float4 a  = ((const float4*)g_agg1)[s * 8 + c];
    float4 xx = ((const float4*)g_xw)[s * 8 + c];
    float4 h;
    h.x = nw * fmaxf(fmaf(d2, xx.x, a.x) + bb.x, 0.f);
    h.y = nw * fmaxf(fmaf(d2, xx.y, a.y) + bb.y, 0.f);
    h.z = nw * fmaxf(fmaf(d2, xx.z, a.z) + bb.z, 0.f);
    h.w = nw * fmaxf(fmaf(d2, xx.w, a.w) + bb.w, 0.f);
    red4(&g_aggh[d * HIDc + c * 4], h);
}

// L4: warp per node — h1(i) inline, v = aggh + d2*h1, shfl matvecs for mu/lv and hi/hj;
//     writes out_mu/out_lv; resets agg1/aggh/deg
__global__ void k_zhij(const float* __restrict__ b1,
                       const float* __restrict__ Wmu, const float* __restrict__ bmu,
                       const float* __restrict__ Wlv, const float* __restrict__ blv,
                       const float* __restrict__ eps,
                       const float* __restrict__ dW1, const float* __restrict__ db1,
                       float* __restrict__ out_mu, float* __restrict__ out_lv) {
    if (threadIdx.x == 0) pdl_trigger();
    int i    = (blockIdx.x * 256 + threadIdx.x) >> 5; // node, 2048 warps
    int lane = threadIdx.x & 31;
    int l    = lane & 15;
    // ---- prologue: everything not written by eagg2 ----
    float bias1 = b1[lane];
    float bmlv  = (lane < 16) ? bmu[l] : blv[l];
    float ev    = eps[i * LATc + l];
    float dbv   = (lane < 16) ? db1[l] : 0.f;
    // ---- dependent part ----
    pdl_wait();
    float deg = g_deg[i];                             // broadcast load
    float d2  = 1.0f / (deg + 1.0f);
    int idx = i * HIDc + lane;
    float aggh = g_aggh[idx];
    float h1 = fmaxf(fmaf(d2, g_xw[idx], g_agg1[idx]) + bias1, 0.f);
    g_agg1[idx] = 0.f; g_aggh[idx] = 0.f;             // reset for next replay
    if (lane == 0) g_deg[i] = 0.f;
    float v = fmaf(d2, h1, aggh);                     // (aggh + d2*h1)

    // mu (lanes 0-15) / logvar (lanes 16-31): 32x16 shfl matvec
    const float* W  = (lane < 16) ? Wmu : Wlv;
    float acc = bmlv;
#pragma unroll
    for (int k = 0; k < HIDc; k++)
        acc = fmaf(__shfl_sync(0xffffffffu, v, k), W[k * LATc + l], acc);
    if (lane < 16) out_mu[i * LATc + l] = acc;
    else           out_lv[i * LATc + l] = acc;

    // z = mu + eps*exp(0.5*lv) in both halves
    float other = __shfl_xor_sync(0xffffffffu, acc, 16);
    float z = (lane < 16) ? fmaf(ev, __expf(0.5f * other), acc)
                          : fmaf(ev, __expf(0.5f * acc), other);

    // hi (lanes 0-15) and hj (lanes 16-31): 16x16 shfl matvecs
    const float* DW = (lane < 16) ? dW1 : dW1 + LATc * LATc;
    float si = dbv;
#pragma unroll
    for (int k = 0; k < LATc; k++)
        si = fmaf(__shfl_sync(0xffffffffu, z, k), DW[k * LATc + l], si);
    if (lane < 16) g_hi[i * LATc + l] = si;
    else           g_hjT[l * Nn + i]  = si;           // transposed for decoder
}

// L5: decoder. packed f32x2 with relu->abs identity (bitwise == scalar relu path):
//   relu(s)*w = (s+|s|)*(w/2) exactly; |s| on packed pair = 2x LOP3 (alu pipe).
//   sigmoid via tanh.approx (1 MUFU): sigma(x) = 0.5 + 0.5*tanh(x/2).
__global__ void __launch_bounds__(256) k_dec(const float* __restrict__ dW2,
                                             const float* __restrict__ db2,
                                             float* __restrict__ adj) {
    __shared__ ull hisp[8][16];                       // (h,h) packed pairs
    int tx = threadIdx.x;
    int j0 = blockIdx.x * 512;
    int i0 = blockIdx.y * 8;
    // ---- prologue: weights/bias (independent of zhij) ----
    ull w2h[LATc];
#pragma unroll
    for (int l = 0; l < LATc; l++) {
        float wh = 0.5f * dW2[l];
        w2h[l] = pack2(wh, wh);
    }
    float b2 = db2[0];
    const ull ABSMASK = 0x7FFFFFFF7FFFFFFFull;
    // ---- dependent part ----
    pdl_wait();
    if (tx < 128) {
        float h = g_hi[(i0 + (tx >> 4)) * LATc + (tx & 15)];
        hisp[tx >> 4][tx & 15] = pack2(h, h);
    }
    ull hjp[LATc];
#pragma unroll
    for (int l = 0; l < LATc; l++)
        hjp[l] = *(const ull*)&g_hjT[l * Nn + j0 + 2 * tx];
    __syncthreads();

    size_t obase = (size_t)i0 * Nn + j0 + 2 * tx;
#pragma unroll
    for (int r = 0; r < 8; r++) {
        ull acc = pack2(b2, b2);
#pragma unroll
        for (int l = 0; l < LATc; l++) {
            ull s = f32x2_add(hisp[r][l], hjp[l]);    // LDS.64 + add.f32x2
            ull u = f32x2_add(s, s & ABSMASK);        // s + |s|  (2x LOP3 on alu pipe)
            acc = f32x2_fma(u, w2h[l], acc);          // * (w/2), accumulate
        }
        float2 sv = unpack2(acc);
        float2 o;
        o.x = fast_sigmoid(sv.x);
        o.y = fast_sigmoid(sv.y);
        *(float2*)&adj[obase + (size_t)r * Nn] = o;
    }
}

// ---------------- launcher: 5 nodes chained with PDL ----------------
template <typename... Args>
static void launch_pdl(void (*kern)(Args...), dim3 grid, dim3 block, Args... args) {
    cudaLaunchConfig_t cfg = {};
    cfg.gridDim = grid; cfg.blockDim = block; cfg.stream = 0;
    cudaLaunchAttribute at[1];
    at[0].id = cudaLaunchAttributeProgrammaticStreamSerialization;
    at[0].val.programmaticStreamSerializationAllowed = 1;
    cfg.attrs = at; cfg.numAttrs = 1;
    if (cudaLaunchKernelEx(&cfg, kern, args...) != cudaSuccess) {
        // fallback: plain serialized launch (pdl_wait degrades to no-op)
        void* pargs[] = { (void*)&args... };
        cudaLaunchKernel((const void*)kern, grid, block, pargs, 0, 0);
    }
}

extern "C" void kernel_launch(void* const* d_in, const int* in_sizes, int n_in,
                              void* d_out, int out_size) {
    const float* x    = (const float*)d_in[0];
    const float* eps  = (const float*)d_in[1];
    const float* W1   = (const float*)d_in[2];
    const float* b1   = (const float*)d_in[3];
    const float* Wmu  = (const float*)d_in[4];
    const float* bmu  = (const float*)d_in[5];
    const float* Wlv  = (const float*)d_in[6];
    const float* blv  = (const float*)d_in[7];
    const float* dW1  = (const float*)d_in[8];
    const float* db1  = (const float*)d_in[9];
    const float* dW2  = (const float*)d_in[10];
    const float* db2  = (const float*)d_in[11];
    const void*  ei   = d_in[12];
    const void*  eit  = d_in[13];

    float* out      = (float*)d_out;
    float* adj_pred = out;
    float* adj_true = out + (size_t)Nn * Nn;
    float* out_mu   = out + 2 * (size_t)Nn * Nn;
    float* out_lv   = out_mu + Nn * LATc;

    launch_pdl(k_pre,       dim3(256), dim3(256), ei, x, W1, (float4*)adj_true);
    launch_pdl(k_eagg1true, dim3(2048), dim3(256), ei, eit, adj_true);
    launch_pdl(k_eagg2,     dim3(2048), dim3(256), ei, b1);
    launch_pdl(k_zhij,      dim3(256), dim3(256), b1, Wmu, bmu, Wlv, blv, eps, dW1, db1, out_mu, out_lv);
    launch_pdl(k_dec,       dim3(4, 256), dim3(256), dW2, db2, adj_pred);
}